// round 15
// baseline (speedup 1.0000x reference)
#include <cuda_runtime.h>
#include <cuda_bf16.h>
#include <cstdint>

// DeformConv: B=8, C=64, H=W=96, COUT=64, 3x3, s=1, p=1, d=1
// R15 (= R14 resubmit; prior round was an infra failure, kernel never ran):
//      R13 (mma.sync bf16 3-term hi/lo split) +
//      - B-fragments loaded via ldmatrix.x2 (halves B-side issue slots/wavefronts)
//      - weight staging via cp.async.cg 16B (removes LDG+STS round-trip)
//      Register-neutral: stays 64 regs -> 4 blocks/SM, single wave.

#define B_    8
#define C_    64
#define H_    96
#define W_    96
#define CO_   64
#define K2_   9
#define NPIX  (H_ * W_)      // 9216
#define TILE  128
#define NTHR  256

// smem layout (bytes)
#define OFF_SIDX 0                    // int2[128]   = 1024
#define OFF_SCF  1024                 // float4[128] = 2048
#define OFF_AH   4096                 // 128*64 bf16 swizzled = 16384
#define OFF_AL   (4096 + 16384)
#define OFF_BH   (4096 + 32768)       // 64 rows * 144B = 9216
#define OFF_BL   (OFF_BH + 9216)
#define SMEM_BYTES (OFF_BL + 9216)    // 55296 -> 4 blocks/SM

// [b][p][c] channel-last x (fp32, 18.9 MB)
__device__ __align__(16) float g_xT[B_ * NPIX * C_];
// [k][o][c] split weights, bf16 (72 KB each)
__device__ __align__(16) __nv_bfloat16 g_wbh[K2_ * CO_ * C_];
__device__ __align__(16) __nv_bfloat16 g_wbl[K2_ * CO_ * C_];

// fused prep: z = 0..7 -> x transpose slice; z == 8 -> weight hi/lo split
__global__ void prep_kernel(const float* __restrict__ x, const float* __restrict__ w) {
    if (blockIdx.z == B_) {
        int idx = (blockIdx.y * gridDim.x + blockIdx.x) * 256 + threadIdx.x;
        if (idx < CO_ * C_ * K2_) {
            int o   = idx / (C_ * K2_);
            int rem = idx % (C_ * K2_);
            int c   = rem / K2_;
            int k   = rem % K2_;
            float v = w[idx];
            __nv_bfloat16 hi = __float2bfloat16_rn(v);
            float lo = v - __bfloat162float(hi);
            g_wbh[(k * CO_ + o) * C_ + c] = hi;
            g_wbl[(k * CO_ + o) * C_ + c] = __float2bfloat16_rn(lo);
        }
        return;
    }
    __shared__ float tl[32][33];
    int b  = blockIdx.z;
    int c0 = blockIdx.y * 32;
    int p0 = blockIdx.x * 32;
    int lane = threadIdx.x & 31;
    int wrp  = threadIdx.x >> 5;
#pragma unroll
    for (int i = 0; i < 4; i++) {
        int cr = wrp * 4 + i;
        tl[cr][lane] = x[((size_t)b * C_ + c0 + cr) * NPIX + p0 + lane];
    }
    __syncthreads();
#pragma unroll
    for (int i = 0; i < 4; i++) {
        int pr = wrp * 4 + i;
        g_xT[((size_t)b * NPIX + p0 + pr) * C_ + c0 + lane] = tl[lane][pr];
    }
}

// ---- helpers ----
typedef unsigned long long ull;
__device__ __forceinline__ void fma2(ull& d, ull a, ull b) {
    asm("fma.rn.f32x2 %0, %1, %2, %0;" : "+l"(d) : "l"(a), "l"(b));
}
__device__ __forceinline__ void mul2(ull& d, ull a, ull b) {
    asm("mul.rn.f32x2 %0, %1, %2;" : "=l"(d) : "l"(a), "l"(b));
}
__device__ __forceinline__ ull pk2(float a, float b) {
    ull r; asm("mov.b64 %0, {%1, %2};" : "=l"(r) : "f"(a), "f"(b)); return r;
}
__device__ __forceinline__ ull splat2(float v) {
    ull r; asm("mov.b64 %0, {%1, %1};" : "=l"(r) : "f"(v)); return r;
}
__device__ __forceinline__ void unpack2(ull v, float& a, float& b) {
    asm("mov.b64 {%0, %1}, %2;" : "=f"(a), "=f"(b) : "l"(v));
}
__device__ __forceinline__ uint32_t bf2(float hi_val, float lo_val) {
    uint32_t r;
    asm("cvt.rn.bf16x2.f32 %0, %1, %2;" : "=r"(r) : "f"(hi_val), "f"(lo_val));
    return r;
}
__device__ __forceinline__ uint32_t smem_u32(const void* p) {
    uint32_t a;
    asm("{ .reg .u64 t; cvta.to.shared.u64 t, %1; cvt.u32.u64 %0, t; }" : "=r"(a) : "l"(p));
    return a;
}
__device__ __forceinline__ uint32_t swz(uint32_t off) {      // SW128
    return off ^ ((off >> 3) & 0x70);
}
__device__ __forceinline__ void ldm4(uint32_t* r, uint32_t addr) {
    asm volatile("ldmatrix.sync.aligned.m8n8.x4.shared.b16 {%0,%1,%2,%3}, [%4];"
                 : "=r"(r[0]), "=r"(r[1]), "=r"(r[2]), "=r"(r[3]) : "r"(addr));
}
__device__ __forceinline__ void ldm2(uint32_t* r, uint32_t addr) {
    asm volatile("ldmatrix.sync.aligned.m8n8.x2.shared.b16 {%0,%1}, [%2];"
                 : "=r"(r[0]), "=r"(r[1]) : "r"(addr));
}
__device__ __forceinline__ void cpa16(uint32_t dst, const void* src) {
    asm volatile("cp.async.cg.shared.global [%0], [%1], 16;" :: "r"(dst), "l"(src) : "memory");
}
__device__ __forceinline__ void mma_bf16(float* d, const uint32_t* a, uint32_t b0, uint32_t b1) {
    asm volatile(
        "mma.sync.aligned.m16n8k16.row.col.f32.bf16.bf16.f32 "
        "{%0,%1,%2,%3}, {%4,%5,%6,%7}, {%8,%9}, {%0,%1,%2,%3};"
        : "+f"(d[0]), "+f"(d[1]), "+f"(d[2]), "+f"(d[3])
        : "r"(a[0]), "r"(a[1]), "r"(a[2]), "r"(a[3]), "r"(b0), "r"(b1));
}

// verified bilinear coord/coefficient fold (x-corner folded into row pair)
__device__ __forceinline__ void coord_fold(int ho, int wo, int k, float offy, float offx,
                                           int2& idx, float4& cfo) {
    float py  = (float)(ho - 1 + k / 3) + offy;
    float pxf = (float)(wo - 1 + k % 3) + offx;
    float y0f = floorf(py), x0f = floorf(pxf);
    float ly = py - y0f,    lx = pxf - x0f;
    int y0 = (int)y0f, x0 = (int)x0f;
    int y1 = y0 + 1,   x1 = x0 + 1;
    float vy0 = (y0 >= 0 && y0 < H_) ? 1.f : 0.f;
    float vy1 = (y1 >= 0 && y1 < H_) ? 1.f : 0.f;
    float vx0 = (x0 >= 0 && x0 < W_) ? 1.f : 0.f;
    float vx1 = (x1 >= 0 && x1 < W_) ? 1.f : 0.f;
    float w00 = (1.f - ly) * (1.f - lx) * vy0 * vx0;
    float w01 = (1.f - ly) * lx         * vy0 * vx1;
    float w10 = ly         * (1.f - lx) * vy1 * vx0;
    float w11 = ly         * lx         * vy1 * vx1;
    int xl = min(max(x0, 0), W_ - 2);
    float s0  = (x0 == xl)     ? 1.f : 0.f;
    float s1  = (x1 == xl)     ? 1.f : 0.f;
    float s0p = (x0 == xl + 1) ? 1.f : 0.f;
    float ca = s0  * w00 + s1 * w01;
    float cb = s0p * w00 + s0 * w01;
    float cc = s0  * w10 + s1 * w11;
    float cd = s0p * w10 + s0 * w11;
    int y0c = min(max(y0, 0), H_ - 1);
    int y1c = min(max(y1, 0), H_ - 1);
    idx = make_int2((y0c * W_ + xl) * C_, (y1c * W_ + xl) * C_);
    cfo = make_float4(ca, cb, cc, cd);
}

__global__ __launch_bounds__(NTHR, 4) void dconv_kernel(
    const float* __restrict__ off,
    float* __restrict__ out)
{
    extern __shared__ __align__(1024) char smraw[];
    const uint32_t smb = smem_u32(smraw);
    int2*   s_idx = (int2*)(smraw + OFF_SIDX);
    float4* s_cf  = (float4*)(smraw + OFF_SCF);

    const int t    = threadIdx.x;
    const int lane = t & 31;
    const int wrp  = t >> 5;
    const int b    = blockIdx.y;
    const int tile_base = blockIdx.x * TILE;

    // gather mapping: 16 channel-groups (4 ch) x 16 pixel-groups
    const int sthr = t & 15;
    const int pg   = t >> 4;

    // A-fragment ldmatrix lane address components
    const int seg  = lane >> 3;
    const int arow = wrp * 16 + (lane & 7) + (seg & 1) * 8;
    const int acol = (seg >> 1) * 16;

    // B-fragment ldmatrix.x2 lane address: rows of staged W (stride 144B),
    // lanes 0-7 -> c0-7 half, lanes 8-15 -> c8-15 half (16-31 ignored)
    const int bb = (lane & 7) * 144 + ((lane >> 3) & 1) * 16;

    int ho = 0, wo = 0;
    if (t < TILE) { int p = tile_base + t; ho = p / W_; wo = p - ho * W_; }
    const float* offb = off + (size_t)b * (2 * K2_) * NPIX + tile_base + t;

    float acc[8][4];
#pragma unroll
    for (int n = 0; n < 8; n++)
#pragma unroll
        for (int i = 0; i < 4; i++) acc[n][i] = 0.f;

    const float* xb = g_xT + (size_t)b * (NPIX * C_);

    for (int k = 0; k < K2_; k++) {
        __syncthreads();   // prev MMA done reading A/B smem

        // ---- stage split weights via cp.async (4 x 16B per thread) ----
        {
            const char* whg = (const char*)(g_wbh + (size_t)k * CO_ * C_);
            const char* wlg = (const char*)(g_wbl + (size_t)k * CO_ * C_);
#pragma unroll
            for (int rep = 0; rep < 2; rep++) {
                int q = t + rep * NTHR;               // 16B chunk 0..511
                int dofs = (q >> 3) * 144 + (q & 7) * 16;
                cpa16(smb + OFF_BH + dofs, whg + q * 16);
                cpa16(smb + OFF_BL + dofs, wlg + q * 16);
            }
            asm volatile("cp.async.commit_group;" ::: "memory");
        }

        // ---- per-pixel coords (t < 128) ----
        if (t < TILE) {
            float offy = __ldg(offb + (size_t)(2 * k    ) * NPIX);
            float offx = __ldg(offb + (size_t)(2 * k + 1) * NPIX);
            int2 ii; float4 cc4;
            coord_fold(ho, wo, k, offy, offx, ii, cc4);
            s_idx[t] = ii;  s_cf[t] = cc4;
        }
        __syncthreads();   // coords visible

        // ---- gather -> split bf16 A tiles (coalesced LDG.128, f32x2 combine) ----
        {
            const int c0 = sthr * 4;
            char* ahb = smraw + OFF_AH;
            char* alb = smraw + OFF_AL;
#pragma unroll 2
            for (int i = 0; i < 8; i++) {
                int pxi = pg + i * 16;
                int2   oo = s_idx[pxi];
                float4 cf = s_cf[pxi];
                float4 va = *(const float4*)(xb + oo.x + c0);
                float4 vb = *(const float4*)(xb + oo.x + C_ + c0);
                float4 vc = *(const float4*)(xb + oo.y + c0);
                float4 vd = *(const float4*)(xb + oo.y + C_ + c0);
                ull r01, r23;
                mul2(r01, splat2(cf.x), pk2(va.x, va.y));
                fma2(r01, splat2(cf.y), pk2(vb.x, vb.y));
                fma2(r01, splat2(cf.z), pk2(vc.x, vc.y));
                fma2(r01, splat2(cf.w), pk2(vd.x, vd.y));
                mul2(r23, splat2(cf.x), pk2(va.z, va.w));
                fma2(r23, splat2(cf.y), pk2(vb.z, vb.w));
                fma2(r23, splat2(cf.z), pk2(vc.z, vc.w));
                fma2(r23, splat2(cf.w), pk2(vd.z, vd.w));
                float f0, f1, f2, f3;
                unpack2(r01, f0, f1);
                unpack2(r23, f2, f3);
                uint32_t h01 = bf2(f1, f0);
                uint32_t h23 = bf2(f3, f2);
                float hf0 = __uint_as_float(h01 << 16);
                float hf1 = __uint_as_float(h01 & 0xFFFF0000u);
                float hf2 = __uint_as_float(h23 << 16);
                float hf3 = __uint_as_float(h23 & 0xFFFF0000u);
                uint32_t l01 = bf2(f1 - hf1, f0 - hf0);
                uint32_t l23 = bf2(f3 - hf3, f2 - hf2);
                uint32_t so = swz((uint32_t)pxi * 128 + c0 * 2);
                *(ull*)(ahb + so) = (ull)h01 | ((ull)h23 << 32);
                *(ull*)(alb + so) = (ull)l01 | ((ull)l23 << 32);
            }
        }
        asm volatile("cp.async.wait_group 0;" ::: "memory");
        __syncthreads();   // A tiles + W stage ready

        // ---- MMA: D[16px x 64o] += A[16px x 64c] * W^T, 3-term split ----
#pragma unroll
        for (int ks = 0; ks < 4; ks++) {
            uint32_t abyte = swz((uint32_t)arow * 128 + ks * 32 + acol);
            uint32_t ah[4], al[4];
            ldm4(ah, smb + OFF_AH + abyte);
            ldm4(al, smb + OFF_AL + abyte);
            uint32_t bofs = (uint32_t)bb + ks * 32;
#pragma unroll
            for (int n = 0; n < 8; n++) {
                uint32_t bh[2], bl[2];
                ldm2(bh, smb + OFF_BH + bofs + n * 1152);
                ldm2(bl, smb + OFF_BL + bofs + n * 1152);
                mma_bf16(acc[n], ah, bh[0], bh[1]);
                mma_bf16(acc[n], al, bh[0], bh[1]);
                mma_bf16(acc[n], ah, bl[0], bl[1]);
            }
        }
    }

    // ---- epilogue: D fragment scatter (rows = px, cols = o) ----
    {
        const int g  = lane >> 2;
        const int tt = lane & 3;
        const int px0 = wrp * 16 + g;
        float* ob = out + ((size_t)b * CO_) * NPIX + tile_base;
#pragma unroll
        for (int n = 0; n < 8; n++) {
            int o = n * 8 + tt * 2;
            ob[(size_t)o       * NPIX + px0    ] = acc[n][0];
            ob[(size_t)(o + 1) * NPIX + px0    ] = acc[n][1];
            ob[(size_t)o       * NPIX + px0 + 8] = acc[n][2];
            ob[(size_t)(o + 1) * NPIX + px0 + 8] = acc[n][3];
        }
    }
}

extern "C" void kernel_launch(void* const* d_in, const int* in_sizes, int n_in,
                              void* d_out, int out_size) {
    const float* x   = (const float*)d_in[0];   // (8, 64, 96, 96)
    const float* off = (const float*)d_in[1];   // (8, 18, 96, 96)
    const float* w   = (const float*)d_in[2];   // (64, 64, 3, 3)
    float* out = (float*)d_out;                 // (8, 64, 96, 96)

    cudaFuncSetAttribute(dconv_kernel,
                         cudaFuncAttributeMaxDynamicSharedMemorySize, SMEM_BYTES);

    dim3 pgrid(NPIX / 32, C_ / 32, B_ + 1);     // (288, 2, 9)
    prep_kernel<<<pgrid, 256>>>(x, w);

    dim3 grid(NPIX / TILE, B_);                 // (72, 8) = 576 blocks
    dconv_kernel<<<grid, NTHR, SMEM_BYTES>>>(off, out);
}

// round 16
// speedup vs baseline: 1.0231x; 1.0231x over previous
#include <cuda_runtime.h>
#include <cuda_bf16.h>
#include <cstdint>

// DeformConv: B=8, C=64, H=W=96, COUT=64, 3x3, s=1, p=1, d=1
// R16: R13 (mma.sync bf16 3-term hi/lo split, scalar-LDS B fragments —
//      the 92.7us path) + cp.async.cg weight staging only.
//      R15's ldmatrix.x2 B-loads reverted: warp-collective .sync loads
//      serialized against the MMA chain (all pipe utilizations dropped).

#define B_    8
#define C_    64
#define H_    96
#define W_    96
#define CO_   64
#define K2_   9
#define NPIX  (H_ * W_)      // 9216
#define TILE  128
#define NTHR  256

// smem layout (bytes)
#define OFF_SIDX 0                    // int2[128]   = 1024
#define OFF_SCF  1024                 // float4[128] = 2048
#define OFF_AH   4096                 // 128*64 bf16 swizzled = 16384
#define OFF_AL   (4096 + 16384)
#define OFF_BH   (4096 + 32768)       // 64 rows * 144B = 9216
#define OFF_BL   (OFF_BH + 9216)
#define SMEM_BYTES (OFF_BL + 9216)    // 55296 -> 4 blocks/SM

// [b][p][c] channel-last x (fp32, 18.9 MB)
__device__ __align__(16) float g_xT[B_ * NPIX * C_];
// [k][o][c] split weights, bf16 (72 KB each)
__device__ __align__(16) __nv_bfloat16 g_wbh[K2_ * CO_ * C_];
__device__ __align__(16) __nv_bfloat16 g_wbl[K2_ * CO_ * C_];

// fused prep: z = 0..7 -> x transpose slice; z == 8 -> weight hi/lo split
__global__ void prep_kernel(const float* __restrict__ x, const float* __restrict__ w) {
    if (blockIdx.z == B_) {
        int idx = (blockIdx.y * gridDim.x + blockIdx.x) * 256 + threadIdx.x;
        if (idx < CO_ * C_ * K2_) {
            int o   = idx / (C_ * K2_);
            int rem = idx % (C_ * K2_);
            int c   = rem / K2_;
            int k   = rem % K2_;
            float v = w[idx];
            __nv_bfloat16 hi = __float2bfloat16_rn(v);
            float lo = v - __bfloat162float(hi);
            g_wbh[(k * CO_ + o) * C_ + c] = hi;
            g_wbl[(k * CO_ + o) * C_ + c] = __float2bfloat16_rn(lo);
        }
        return;
    }
    __shared__ float tl[32][33];
    int b  = blockIdx.z;
    int c0 = blockIdx.y * 32;
    int p0 = blockIdx.x * 32;
    int lane = threadIdx.x & 31;
    int wrp  = threadIdx.x >> 5;
#pragma unroll
    for (int i = 0; i < 4; i++) {
        int cr = wrp * 4 + i;
        tl[cr][lane] = x[((size_t)b * C_ + c0 + cr) * NPIX + p0 + lane];
    }
    __syncthreads();
#pragma unroll
    for (int i = 0; i < 4; i++) {
        int pr = wrp * 4 + i;
        g_xT[((size_t)b * NPIX + p0 + pr) * C_ + c0 + lane] = tl[lane][pr];
    }
}

// ---- helpers ----
typedef unsigned long long ull;
__device__ __forceinline__ void fma2(ull& d, ull a, ull b) {
    asm("fma.rn.f32x2 %0, %1, %2, %0;" : "+l"(d) : "l"(a), "l"(b));
}
__device__ __forceinline__ void mul2(ull& d, ull a, ull b) {
    asm("mul.rn.f32x2 %0, %1, %2;" : "=l"(d) : "l"(a), "l"(b));
}
__device__ __forceinline__ ull pk2(float a, float b) {
    ull r; asm("mov.b64 %0, {%1, %2};" : "=l"(r) : "f"(a), "f"(b)); return r;
}
__device__ __forceinline__ ull splat2(float v) {
    ull r; asm("mov.b64 %0, {%1, %1};" : "=l"(r) : "f"(v)); return r;
}
__device__ __forceinline__ void unpack2(ull v, float& a, float& b) {
    asm("mov.b64 {%0, %1}, %2;" : "=f"(a), "=f"(b) : "l"(v));
}
__device__ __forceinline__ uint32_t bf2(float hi_val, float lo_val) {
    uint32_t r;
    asm("cvt.rn.bf16x2.f32 %0, %1, %2;" : "=r"(r) : "f"(hi_val), "f"(lo_val));
    return r;
}
__device__ __forceinline__ uint32_t smem_u32(const void* p) {
    uint32_t a;
    asm("{ .reg .u64 t; cvta.to.shared.u64 t, %1; cvt.u32.u64 %0, t; }" : "=r"(a) : "l"(p));
    return a;
}
__device__ __forceinline__ uint32_t swz(uint32_t off) {      // SW128
    return off ^ ((off >> 3) & 0x70);
}
__device__ __forceinline__ void ldm4(uint32_t* r, uint32_t addr) {
    asm volatile("ldmatrix.sync.aligned.m8n8.x4.shared.b16 {%0,%1,%2,%3}, [%4];"
                 : "=r"(r[0]), "=r"(r[1]), "=r"(r[2]), "=r"(r[3]) : "r"(addr));
}
__device__ __forceinline__ void cpa16(uint32_t dst, const void* src) {
    asm volatile("cp.async.cg.shared.global [%0], [%1], 16;" :: "r"(dst), "l"(src) : "memory");
}
__device__ __forceinline__ void mma_bf16(float* d, const uint32_t* a, uint32_t b0, uint32_t b1) {
    asm volatile(
        "mma.sync.aligned.m16n8k16.row.col.f32.bf16.bf16.f32 "
        "{%0,%1,%2,%3}, {%4,%5,%6,%7}, {%8,%9}, {%0,%1,%2,%3};"
        : "+f"(d[0]), "+f"(d[1]), "+f"(d[2]), "+f"(d[3])
        : "r"(a[0]), "r"(a[1]), "r"(a[2]), "r"(a[3]), "r"(b0), "r"(b1));
}

// verified bilinear coord/coefficient fold (x-corner folded into row pair)
__device__ __forceinline__ void coord_fold(int ho, int wo, int k, float offy, float offx,
                                           int2& idx, float4& cfo) {
    float py  = (float)(ho - 1 + k / 3) + offy;
    float pxf = (float)(wo - 1 + k % 3) + offx;
    float y0f = floorf(py), x0f = floorf(pxf);
    float ly = py - y0f,    lx = pxf - x0f;
    int y0 = (int)y0f, x0 = (int)x0f;
    int y1 = y0 + 1,   x1 = x0 + 1;
    float vy0 = (y0 >= 0 && y0 < H_) ? 1.f : 0.f;
    float vy1 = (y1 >= 0 && y1 < H_) ? 1.f : 0.f;
    float vx0 = (x0 >= 0 && x0 < W_) ? 1.f : 0.f;
    float vx1 = (x1 >= 0 && x1 < W_) ? 1.f : 0.f;
    float w00 = (1.f - ly) * (1.f - lx) * vy0 * vx0;
    float w01 = (1.f - ly) * lx         * vy0 * vx1;
    float w10 = ly         * (1.f - lx) * vy1 * vx0;
    float w11 = ly         * lx         * vy1 * vx1;
    int xl = min(max(x0, 0), W_ - 2);
    float s0  = (x0 == xl)     ? 1.f : 0.f;
    float s1  = (x1 == xl)     ? 1.f : 0.f;
    float s0p = (x0 == xl + 1) ? 1.f : 0.f;
    float ca = s0  * w00 + s1 * w01;
    float cb = s0p * w00 + s0 * w01;
    float cc = s0  * w10 + s1 * w11;
    float cd = s0p * w10 + s0 * w11;
    int y0c = min(max(y0, 0), H_ - 1);
    int y1c = min(max(y1, 0), H_ - 1);
    idx = make_int2((y0c * W_ + xl) * C_, (y1c * W_ + xl) * C_);
    cfo = make_float4(ca, cb, cc, cd);
}

__global__ __launch_bounds__(NTHR, 4) void dconv_kernel(
    const float* __restrict__ off,
    float* __restrict__ out)
{
    extern __shared__ __align__(1024) char smraw[];
    const uint32_t smb = smem_u32(smraw);
    int2*   s_idx = (int2*)(smraw + OFF_SIDX);
    float4* s_cf  = (float4*)(smraw + OFF_SCF);

    const int t    = threadIdx.x;
    const int lane = t & 31;
    const int wrp  = t >> 5;
    const int b    = blockIdx.y;
    const int tile_base = blockIdx.x * TILE;

    // gather mapping: 16 channel-groups (4 ch) x 16 pixel-groups
    const int sthr = t & 15;
    const int pg   = t >> 4;

    // A-fragment ldmatrix lane address components
    const int seg  = lane >> 3;
    const int arow = wrp * 16 + (lane & 7) + (seg & 1) * 8;
    const int acol = (seg >> 1) * 16;

    // B-fragment scalar-LDS components (u32 view of staged W, stride 36 u32)
    const int bo = lane >> 2;                         // n within 8-tile
    const int bc = lane & 3;                          // k-pair
    const int bthr = bo * 36 + bc;

    int ho = 0, wo = 0;
    if (t < TILE) { int p = tile_base + t; ho = p / W_; wo = p - ho * W_; }
    const float* offb = off + (size_t)b * (2 * K2_) * NPIX + tile_base + t;

    float acc[8][4];
#pragma unroll
    for (int n = 0; n < 8; n++)
#pragma unroll
        for (int i = 0; i < 4; i++) acc[n][i] = 0.f;

    const float* xb = g_xT + (size_t)b * (NPIX * C_);

    for (int k = 0; k < K2_; k++) {
        __syncthreads();   // prev MMA done reading A/B smem

        // ---- stage split weights via cp.async (4 x 16B per thread) ----
        // dest (q>>3)*144 + (q&7)*16  ==  word layout o*36 + cword (R13's)
        {
            const char* whg = (const char*)(g_wbh + (size_t)k * CO_ * C_);
            const char* wlg = (const char*)(g_wbl + (size_t)k * CO_ * C_);
#pragma unroll
            for (int rep = 0; rep < 2; rep++) {
                int q = t + rep * NTHR;               // 16B chunk 0..511
                int dofs = (q >> 3) * 144 + (q & 7) * 16;
                cpa16(smb + OFF_BH + dofs, whg + q * 16);
                cpa16(smb + OFF_BL + dofs, wlg + q * 16);
            }
            asm volatile("cp.async.commit_group;" ::: "memory");
        }

        // ---- per-pixel coords (t < 128) ----
        if (t < TILE) {
            float offy = __ldg(offb + (size_t)(2 * k    ) * NPIX);
            float offx = __ldg(offb + (size_t)(2 * k + 1) * NPIX);
            int2 ii; float4 cc4;
            coord_fold(ho, wo, k, offy, offx, ii, cc4);
            s_idx[t] = ii;  s_cf[t] = cc4;
        }
        __syncthreads();   // coords visible

        // ---- gather -> split bf16 A tiles (coalesced LDG.128, f32x2 combine) ----
        {
            const int c0 = sthr * 4;
            char* ahb = smraw + OFF_AH;
            char* alb = smraw + OFF_AL;
#pragma unroll 2
            for (int i = 0; i < 8; i++) {
                int pxi = pg + i * 16;
                int2   oo = s_idx[pxi];
                float4 cf = s_cf[pxi];
                float4 va = *(const float4*)(xb + oo.x + c0);
                float4 vb = *(const float4*)(xb + oo.x + C_ + c0);
                float4 vc = *(const float4*)(xb + oo.y + c0);
                float4 vd = *(const float4*)(xb + oo.y + C_ + c0);
                ull r01, r23;
                mul2(r01, splat2(cf.x), pk2(va.x, va.y));
                fma2(r01, splat2(cf.y), pk2(vb.x, vb.y));
                fma2(r01, splat2(cf.z), pk2(vc.x, vc.y));
                fma2(r01, splat2(cf.w), pk2(vd.x, vd.y));
                mul2(r23, splat2(cf.x), pk2(va.z, va.w));
                fma2(r23, splat2(cf.y), pk2(vb.z, vb.w));
                fma2(r23, splat2(cf.z), pk2(vc.z, vc.w));
                fma2(r23, splat2(cf.w), pk2(vd.z, vd.w));
                float f0, f1, f2, f3;
                unpack2(r01, f0, f1);
                unpack2(r23, f2, f3);
                uint32_t h01 = bf2(f1, f0);
                uint32_t h23 = bf2(f3, f2);
                float hf0 = __uint_as_float(h01 << 16);
                float hf1 = __uint_as_float(h01 & 0xFFFF0000u);
                float hf2 = __uint_as_float(h23 << 16);
                float hf3 = __uint_as_float(h23 & 0xFFFF0000u);
                uint32_t l01 = bf2(f1 - hf1, f0 - hf0);
                uint32_t l23 = bf2(f3 - hf3, f2 - hf2);
                uint32_t so = swz((uint32_t)pxi * 128 + c0 * 2);
                *(ull*)(ahb + so) = (ull)h01 | ((ull)h23 << 32);
                *(ull*)(alb + so) = (ull)l01 | ((ull)l23 << 32);
            }
        }
        asm volatile("cp.async.wait_group 0;" ::: "memory");
        __syncthreads();   // A tiles + W stage ready

        // ---- MMA: D[16px x 64o] += A[16px x 64c] * W^T, 3-term split ----
        {
            const uint32_t* bhp = (const uint32_t*)(smraw + OFF_BH);
            const uint32_t* blp = (const uint32_t*)(smraw + OFF_BL);
#pragma unroll
            for (int ks = 0; ks < 4; ks++) {
                uint32_t abyte = swz((uint32_t)arow * 128 + ks * 32 + acol);
                uint32_t ah[4], al[4];
                ldm4(ah, smb + OFF_AH + abyte);
                ldm4(al, smb + OFF_AL + abyte);
                const int kw = ks * 8 + bthr;
#pragma unroll
                for (int n = 0; n < 8; n++) {
                    int wi = n * (8 * 36) + kw;
                    uint32_t bh0 = bhp[wi], bh1 = bhp[wi + 4];
                    uint32_t bl0 = blp[wi], bl1 = blp[wi + 4];
                    mma_bf16(acc[n], ah, bh0, bh1);
                    mma_bf16(acc[n], al, bh0, bh1);
                    mma_bf16(acc[n], ah, bl0, bl1);
                }
            }
        }
    }

    // ---- epilogue: D fragment scatter (rows = px, cols = o) ----
    {
        const int g  = lane >> 2;
        const int tt = lane & 3;
        const int px0 = wrp * 16 + g;
        float* ob = out + ((size_t)b * CO_) * NPIX + tile_base;
#pragma unroll
        for (int n = 0; n < 8; n++) {
            int o = n * 8 + tt * 2;
            ob[(size_t)o       * NPIX + px0    ] = acc[n][0];
            ob[(size_t)(o + 1) * NPIX + px0    ] = acc[n][1];
            ob[(size_t)o       * NPIX + px0 + 8] = acc[n][2];
            ob[(size_t)(o + 1) * NPIX + px0 + 8] = acc[n][3];
        }
    }
}

extern "C" void kernel_launch(void* const* d_in, const int* in_sizes, int n_in,
                              void* d_out, int out_size) {
    const float* x   = (const float*)d_in[0];   // (8, 64, 96, 96)
    const float* off = (const float*)d_in[1];   // (8, 18, 96, 96)
    const float* w   = (const float*)d_in[2];   // (64, 64, 3, 3)
    float* out = (float*)d_out;                 // (8, 64, 96, 96)

    cudaFuncSetAttribute(dconv_kernel,
                         cudaFuncAttributeMaxDynamicSharedMemorySize, SMEM_BYTES);

    dim3 pgrid(NPIX / 32, C_ / 32, B_ + 1);     // (288, 2, 9)
    prep_kernel<<<pgrid, 256>>>(x, w);

    dim3 grid(NPIX / TILE, B_);                 // (72, 8) = 576 blocks
    dconv_kernel<<<grid, NTHR, SMEM_BYTES>>>(off, out);
}